// round 17
// baseline (speedup 1.0000x reference)
#include <cuda_runtime.h>
#include <cstdint>

#define NSESS   4096
#define NTRIALS 2048
#define HALFT   1024            // trials per warp (half session)
#define FWARM   16              // warmup trials (validated: rel_err ~6e-5)

#define GBYTES  3072            // one group = 256 trials = 3072 B
#define WBUF    (3 * GBYTES)    // ring-3 per warp = 9216 B

__device__ __forceinline__ float frcp_fast(float x) {
    float y;
    asm("rcp.approx.f32 %0, %1;" : "=f"(y) : "f"(x));
    return y;
}

__device__ __forceinline__ void cp_async16(uint32_t dst, const void* src) {
    asm volatile("cp.async.cg.shared.global [%0], [%1], 16;\n" :: "r"(dst), "l"(src));
}
__device__ __forceinline__ void cp_commit() {
    asm volatile("cp.async.commit_group;\n" ::: "memory");
}
template <int N>
__device__ __forceinline__ void cp_wait() {
    asm volatile("cp.async.wait_group %0;\n" :: "n"(N) : "memory");
}

// ---------------------------------------------------------------------------
// Fused kernel v2 (R16 structure, ring-3 staging for occupancy).
// One warp = one HALF-session; lane l = trials [l*32, l*32+32) (+16 warmup).
//   input: 4 groups x 3 KB through a 3-buffer ring (cp.async, 3-deep)
//   pack:  8 ballots per group; lane l keeps word l
//   filter: R13-proven recurrence; output staged per 16-trial half (4.6 KB,
//           reusing ring buffers), flushed as coalesced STG.128
// smem 36.9 KB/block + <=85 regs (launch_bounds 128,6) -> 6 blocks/SM.
// ---------------------------------------------------------------------------
__global__ void __launch_bounds__(128, 6)
fused_kernel(const float* __restrict__ in,
             const float* __restrict__ p_stay_raw,
             const float* __restrict__ c_raw,
             float* __restrict__ out) {
    __shared__ __align__(16) char buf[4][WBUF];   // 36864 B/block

    const int lane  = threadIdx.x & 31;
    const int wid   = threadIdx.x >> 5;
    const int gwarp = blockIdx.x * 4 + wid;
    const int s     = gwarp >> 1;
    const int h     = gwarp & 1;

    const char* src = (const char*)in + (long)s * (NTRIALS * 12) + h * (HALFT * 12);
    const uint32_t sb = (uint32_t)__cvta_generic_to_shared(&buf[wid][0]);

    // ---- issue groups 0,1,2 into ring slots 0,1,2 ----
#pragma unroll
    for (int g = 0; g < 3; g++) {
#pragma unroll
        for (int r = 0; r < 6; r++)
            cp_async16(sb + g * GBYTES + r * 512 + lane * 16,
                       src + g * GBYTES + r * 512 + lane * 16);
        cp_commit();
    }

    // model constants (overlap with cp.async latency)
    const float pv = 1.0f / (1.0f + __expf(-p_stay_raw[0]));
    const float cv = 1.0f / (1.0f + __expf(-c_raw[0]));
    const float A  = 0.5f * (1.0f + cv);
    const float B  = 0.5f * (1.0f - cv);
    const float q  = 0.5f * (1.0f + pv);
    const float qm = 0.5f * (1.0f - pv);

    // ---- h==1: pack previous half's last 16 trials from global ----
    uint32_t pw = 0;
    if (h) {
        const float* gp = in + ((long)s * NTRIALS + HALFT - 16 + (lane & 15)) * 3;
        float cl = gp[0];
        float o  = gp[2];
        pw = __ballot_sync(0xFFFFFFFFu, (lane < 16) && (cl == o)) << 16;
    }

    // ---- pack 4 groups through the ring; lane l keeps word l ----
    uint32_t myw = 0;
#pragma unroll
    for (int g = 0; g < 4; g++) {
        // drain: before g=0 two commits may remain outstanding (c0 done);
        // after issuing c3, before g=1 wait c1, etc.
        switch (g) {
            case 0: cp_wait<2>(); break;
            case 1: cp_wait<2>(); break;
            case 2: cp_wait<1>(); break;
            default: cp_wait<0>(); break;
        }
        __syncwarp();

        const float* sf = (const float*)&buf[wid][(g & 3) % 3 * GBYTES];
#pragma unroll
        for (int k = 0; k < 8; k++) {
            float cl = sf[k * 96 + lane * 3];
            float o  = sf[k * 96 + lane * 3 + 2];
            uint32_t bits = __ballot_sync(0xFFFFFFFFu, cl == o);
            const int w = g * 8 + k;
            if (lane == w) myw = bits;
        }

        // after group 0's last ballot (warp-synced), slot 0 is dead:
        // issue group 3 into it
        if (g == 0) {
#pragma unroll
            for (int r = 0; r < 6; r++)
                cp_async16(sb + 0 * GBYTES + r * 512 + lane * 16,
                           src + 3 * GBYTES + r * 512 + lane * 16);
            cp_commit();
        }
    }

    // ---- warmup word: high 16 bits of previous lane's word ----
    uint32_t wp = __shfl_up_sync(0xFFFFFFFFu, myw, 1);
    if (lane == 0) wp = pw;

    // ---- filter (R13-proven math) ----
    float v0 = 0.5f, v1 = 0.5f;

    if (h + lane) {
#pragma unroll
        for (int i = 0; i < FWARM; i++) {
            float e0 = ((wp >> (16 + i)) & 1u) ? A : B;
            float u0 = e0 * v0;
            float u1 = fmaf(-e0, v1, v1);
            float sm = u0 + u1;
            float a  = fmaf(q, u0, qm * u1);
            v0 = a;
            v1 = sm - a;
        }
        float r = frcp_fast(v0 + v1);
        v0 *= r; v1 *= r;
    }

    __syncwarp();
    float4* stage4 = (float4*)&buf[wid][0];
    float4* ob4 = stage4 + lane * 9;     // 144 B stride: conflict-free STS.128
    float4* og4 = (float4*)out + (long)s * (NTRIALS / 2) + h * (HALFT / 2);

#pragma unroll
    for (int g = 0; g < 2; g++) {
        float rlast = 1.0f;
        float px = 0.0f;
#pragma unroll
        for (int i = 0; i < 16; i++) {
            float e0 = ((myw >> (g * 16 + i)) & 1u) ? A : B;
            float u0 = e0 * v0;
            float u1 = fmaf(-e0, v1, v1);
            float sm = u0 + u1;
            float a  = fmaf(q, u0, qm * u1);
            float r  = frcp_fast(sm);       // off-chain: outputs only
            float x  = a * r;
            if (i & 1) {
                ob4[i >> 1] = make_float4(px, 1.0f - px, x, 1.0f - x);
            } else {
                px = x;
            }
            if (i == 15) rlast = r;
            v0 = a;
            v1 = sm - a;
        }
        v0 *= rlast; v1 *= rlast;           // exact renorm, off the chain tail

        __syncwarp();
        // flush this half: output float4 index = row*16 + g*8 + col
#pragma unroll
        for (int j = 0; j < 8; j++) {
            int flat = j * 32 + lane;        // 0..255
            int row = flat >> 3;
            int col = flat & 7;
            og4[row * 16 + g * 8 + col] = stage4[row * 9 + col];
        }
        __syncwarp();
    }
}

extern "C" void kernel_launch(void* const* d_in, const int* in_sizes, int n_in,
                              void* d_out, int out_size) {
    const float* in   = (const float*)d_in[0];
    const float* praw = (const float*)d_in[1];
    const float* craw = (const float*)d_in[2];
    float* out = (float*)d_out;

    // 4096 sessions x 2 halves = 8192 warps = 2048 blocks of 128 threads
    fused_kernel<<<NSESS * 2 / 4, 128>>>(in, praw, craw, out);
}